// round 2
// baseline (speedup 1.0000x reference)
#include <cuda_runtime.h>

// Problem constants
#define NN     2048
#define MULS   128
#define DIN    9
#define NPAIR  45
#define NTRI   165

// Duplicated-channel basis layout (each channel stored twice: [c,c] so one
// 16B LDS yields two f32x2-broadcast operands):
//  A block:   9 rows * 4 ch * 2 =  72 floats
//  B block:  45 rows * 10 ch * 2 = 900 floats (9 real ch + 1 pad)
//  C block: 165 rows * 10 ch * 2 = 3300 floats
#define OFF_A_F 0
#define OFF_B_F 72
#define OFF_C_F 972
#define BS_TOTAL 4272   // floats

__device__ float gBs[BS_TOTAL];

typedef unsigned long long u64;

__device__ __forceinline__ u64 pk2(float lo, float hi) {
    u64 r; asm("mov.b64 %0, {%1, %2};" : "=l"(r) : "f"(lo), "f"(hi)); return r;
}
__device__ __forceinline__ void upk2(float& lo, float& hi, u64 v) {
    asm("mov.b64 {%0, %1}, %2;" : "=f"(lo), "=f"(hi) : "l"(v));
}
__device__ __forceinline__ u64 ffma2(u64 a, u64 b, u64 c) {
    u64 d; asm("fma.rn.f32x2 %0, %1, %2, %3;" : "=l"(d) : "l"(a), "l"(b), "l"(c)); return d;
}
__device__ __forceinline__ u64 fmul2(u64 a, u64 b) {
    u64 d; asm("mul.rn.f32x2 %0, %1, %2;" : "=l"(d) : "l"(a), "l"(b)); return d;
}

// ---------------------------------------------------------------------------
// Prep: symmetrize bases onto sorted multisets, duplicated-channel layout.
// ---------------------------------------------------------------------------
__global__ void prep_kernel(const float* __restrict__ b0, const float* __restrict__ b1,
                            const float* __restrict__ b2, const float* __restrict__ b3,
                            const float* __restrict__ b4, const float* __restrict__ b5)
{
    const int t = threadIdx.x;

    // nu=1 rows: channels [e0(1), e1(3)]
    if (t < DIN) {
        float* row = gBs + OFF_A_F + t * 8;
        row[0] = row[1] = b0[t];
        for (int p = 0; p < 3; p++)
            row[2 + 2 * p] = row[3 + 2 * p] = b1[t * 3 + p];
    }

    // nu=2 rows: channels [e2 s0..2, e3 s0p0..s1p2, pad]
    if (t < NPAIR) {
        int a = 0, b = 0, idx = 0;
        for (int i = 0; i < DIN; i++)
            for (int j = i; j < DIN; j++) {
                if (idx == t) { a = i; b = j; }
                idx++;
            }
        float* row = gBs + OFF_B_F + t * 20;
        for (int s = 0; s < 3; s++) {
            float v = b2[(a * 9 + b) * 3 + s];
            if (a != b) v += b2[(b * 9 + a) * 3 + s];
            row[2 * s] = row[2 * s + 1] = v;
        }
        for (int s = 0; s < 2; s++)
            for (int p = 0; p < 3; p++) {
                float v = b3[((a * 9 + b) * 2 + s) * 3 + p];
                if (a != b) v += b3[((b * 9 + a) * 2 + s) * 3 + p];
                int q = 3 + s * 3 + p;
                row[2 * q] = row[2 * q + 1] = v;
            }
        row[18] = row[19] = 0.f;
    }

    // nu=3 rows: channels [e4 s0..3, e5 s0p0..s1p2]
    if (t < NTRI) {
        int a = 0, b = 0, c = 0, idx = 0;
        for (int i = 0; i < DIN; i++)
            for (int j = i; j < DIN; j++)
                for (int k = j; k < DIN; k++) {
                    if (idx == t) { a = i; b = j; c = k; }
                    idx++;
                }
        int pi[6] = {a, a, b, b, c, c};
        int pj[6] = {b, c, a, c, a, b};
        int pk[6] = {c, b, c, a, b, a};
        float acc[10];
        #pragma unroll
        for (int q = 0; q < 10; q++) acc[q] = 0.f;

        for (int q = 0; q < 6; q++) {
            bool dup = false;
            for (int r = 0; r < q; r++)
                if (pi[r] == pi[q] && pj[r] == pj[q] && pk[r] == pk[q]) { dup = true; break; }
            if (dup) continue;
            const int base = (pi[q] * 9 + pj[q]) * 9 + pk[q];
            for (int s = 0; s < 4; s++) acc[s] += b4[base * 4 + s];
            for (int s = 0; s < 2; s++)
                for (int p = 0; p < 3; p++)
                    acc[4 + s * 3 + p] += b5[(base * 2 + s) * 3 + p];
        }
        float* row = gBs + OFF_C_F + t * 20;
        #pragma unroll
        for (int q = 0; q < 10; q++)
            row[2 * q] = row[2 * q + 1] = acc[q];
    }
}

// ---------------------------------------------------------------------------
// Main kernel: one thread per (node, {m, m+64}) — 2 items via fma.rn.f32x2.
// blockDim = (64, 4): 4 nodes per block.
// ---------------------------------------------------------------------------
__global__ void __launch_bounds__(256, 2)
symcon_kernel(const float* __restrict__ feats,   // (N, 1152)
              const int*   __restrict__ species, // (N,)
              const float* __restrict__ W0, const float* __restrict__ W1,
              const float* __restrict__ W2, const float* __restrict__ W3,
              const float* __restrict__ W4, const float* __restrict__ W5,
              float* __restrict__ out)            // (N, 512)
{
    __shared__ float4 s4[BS_TOTAL / 4];   // 1068 float4 = 17088 B

    const int tid = threadIdx.y * 64 + threadIdx.x;
    {
        const float4* g4 = reinterpret_cast<const float4*>(gBs);
        #pragma unroll
        for (int i = tid; i < BS_TOTAL / 4; i += 256) s4[i] = g4[i];
    }
    __syncthreads();

    // view shared basis as pairs of packed-duplicate u64 channels
    const ulonglong2* s2 = reinterpret_cast<const ulonglong2*>(s4);
    const ulonglong2* sA = s2;          // u2 idx 0..17   (row a: a*2 + j)
    const ulonglong2* sB = s2 + 18;     // row pr: pr*5 + j
    const ulonglong2* sC = s2 + 243;    // row t3: t3*5 + j

    const int m0 = threadIdx.x;         // 0..63
    const int m1 = m0 + 64;
    const int n  = blockIdx.x * 4 + threadIdx.y;
    const int e  = species[n];

    const float* fbase = feats + n * 1152;

    // packed features: lo = item m0, hi = item m1
    u64 f2[9];
    f2[0] = pk2(fbase[m0], fbase[m1]);
    #pragma unroll
    for (int k = 0; k < 3; k++)
        f2[1 + k] = pk2(fbase[128 + m0 * 3 + k], fbase[128 + m1 * 3 + k]);
    #pragma unroll
    for (int k = 0; k < 5; k++)
        f2[4 + k] = pk2(fbase[512 + m0 * 5 + k], fbase[512 + m1 * 5 + k]);

    // nu=1: TA[4]
    u64 TA[4] = {0ull, 0ull, 0ull, 0ull};
    #pragma unroll
    for (int a = 0; a < 9; a++) {
        const ulonglong2 v0 = sA[a * 2 + 0];
        const ulonglong2 v1 = sA[a * 2 + 1];
        TA[0] = ffma2(v0.x, f2[a], TA[0]);
        TA[1] = ffma2(v0.y, f2[a], TA[1]);
        TA[2] = ffma2(v1.x, f2[a], TA[2]);
        TA[3] = ffma2(v1.y, f2[a], TA[3]);
    }

    // nu=2 + nu=3 fused
    u64 TB[9];
    #pragma unroll
    for (int q = 0; q < 9; q++) TB[q] = 0ull;
    u64 TC[10];
    #pragma unroll
    for (int q = 0; q < 10; q++) TC[q] = 0ull;

    {
        int pr = 0, t3 = 0;
        #pragma unroll
        for (int a = 0; a < 9; a++) {
            #pragma unroll
            for (int b = a; b < 9; b++) {
                const u64 Pab = fmul2(f2[a], f2[b]);

                // nu=2 row pr (channels 0..8; ch9 is pad)
                {
                    const ulonglong2 v0 = sB[pr * 5 + 0];
                    const ulonglong2 v1 = sB[pr * 5 + 1];
                    const ulonglong2 v2 = sB[pr * 5 + 2];
                    const ulonglong2 v3 = sB[pr * 5 + 3];
                    const ulonglong2 v4 = sB[pr * 5 + 4];
                    TB[0] = ffma2(v0.x, Pab, TB[0]);
                    TB[1] = ffma2(v0.y, Pab, TB[1]);
                    TB[2] = ffma2(v1.x, Pab, TB[2]);
                    TB[3] = ffma2(v1.y, Pab, TB[3]);
                    TB[4] = ffma2(v2.x, Pab, TB[4]);
                    TB[5] = ffma2(v2.y, Pab, TB[5]);
                    TB[6] = ffma2(v3.x, Pab, TB[6]);
                    TB[7] = ffma2(v3.y, Pab, TB[7]);
                    TB[8] = ffma2(v4.x, Pab, TB[8]);
                }

                // nu=3 rows (c >= b)
                #pragma unroll
                for (int c = b; c < 9; c++) {
                    const u64 Fv = fmul2(Pab, f2[c]);
                    const ulonglong2 v0 = sC[t3 * 5 + 0];
                    const ulonglong2 v1 = sC[t3 * 5 + 1];
                    const ulonglong2 v2 = sC[t3 * 5 + 2];
                    const ulonglong2 v3 = sC[t3 * 5 + 3];
                    const ulonglong2 v4 = sC[t3 * 5 + 4];
                    TC[0] = ffma2(v0.x, Fv, TC[0]);
                    TC[1] = ffma2(v0.y, Fv, TC[1]);
                    TC[2] = ffma2(v1.x, Fv, TC[2]);
                    TC[3] = ffma2(v1.y, Fv, TC[3]);
                    TC[4] = ffma2(v2.x, Fv, TC[4]);
                    TC[5] = ffma2(v2.y, Fv, TC[5]);
                    TC[6] = ffma2(v3.x, Fv, TC[6]);
                    TC[7] = ffma2(v3.y, Fv, TC[7]);
                    TC[8] = ffma2(v4.x, Fv, TC[8]);
                    TC[9] = ffma2(v4.y, Fv, TC[9]);
                    t3++;
                }
                pr++;
            }
        }
    }

    // weight contraction (packed over the two items)
    u64 o0;
    {
        const u64 w0 = pk2(W0[e * 128 + m0], W0[e * 128 + m1]);
        o0 = fmul2(w0, TA[0]);
        #pragma unroll
        for (int s = 0; s < 3; s++) {
            const u64 w = pk2(W2[(e * 3 + s) * 128 + m0], W2[(e * 3 + s) * 128 + m1]);
            o0 = ffma2(w, TB[s], o0);
        }
        #pragma unroll
        for (int s = 0; s < 4; s++) {
            const u64 w = pk2(W4[(e * 4 + s) * 128 + m0], W4[(e * 4 + s) * 128 + m1]);
            o0 = ffma2(w, TC[s], o0);
        }
    }
    u64 o1[3];
    {
        const u64 w1 = pk2(W1[e * 128 + m0], W1[e * 128 + m1]);
        #pragma unroll
        for (int p = 0; p < 3; p++) o1[p] = fmul2(w1, TA[1 + p]);
        #pragma unroll
        for (int s = 0; s < 2; s++) {
            const u64 w = pk2(W3[(e * 2 + s) * 128 + m0], W3[(e * 2 + s) * 128 + m1]);
            #pragma unroll
            for (int p = 0; p < 3; p++) o1[p] = ffma2(w, TB[3 + s * 3 + p], o1[p]);
        }
        #pragma unroll
        for (int s = 0; s < 2; s++) {
            const u64 w = pk2(W5[(e * 2 + s) * 128 + m0], W5[(e * 2 + s) * 128 + m1]);
            #pragma unroll
            for (int p = 0; p < 3; p++) o1[p] = ffma2(w, TC[4 + s * 3 + p], o1[p]);
        }
    }

    // output: (N, 512) = [l0: (N,128)] ++ [l1: (N,128,3)]
    float* obase = out + n * 512;
    float lo, hi;
    upk2(lo, hi, o0);
    obase[m0] = lo;
    obase[m1] = hi;
    #pragma unroll
    for (int p = 0; p < 3; p++) {
        upk2(lo, hi, o1[p]);
        obase[128 + m0 * 3 + p] = lo;
        obase[128 + m1 * 3 + p] = hi;
    }
}

// ---------------------------------------------------------------------------
extern "C" void kernel_launch(void* const* d_in, const int* in_sizes, int n_in,
                              void* d_out, int out_size)
{
    const float* feats   = (const float*)d_in[0];
    const int*   species = (const int*)  d_in[1];
    const float* b0 = (const float*)d_in[2];
    const float* w0 = (const float*)d_in[3];
    const float* b1 = (const float*)d_in[4];
    const float* w1 = (const float*)d_in[5];
    const float* b2 = (const float*)d_in[6];
    const float* w2 = (const float*)d_in[7];
    const float* b3 = (const float*)d_in[8];
    const float* w3 = (const float*)d_in[9];
    const float* b4 = (const float*)d_in[10];
    const float* w4 = (const float*)d_in[11];
    const float* b5 = (const float*)d_in[12];
    const float* w5 = (const float*)d_in[13];
    float* out = (float*)d_out;

    prep_kernel<<<1, 256>>>(b0, b1, b2, b3, b4, b5);

    dim3 block(64, 4);
    dim3 grid(NN / 4);
    symcon_kernel<<<grid, block>>>(feats, species, w0, w1, w2, w3, w4, w5, out);
}

// round 3
// speedup vs baseline: 1.5340x; 1.5340x over previous
#include <cuda_runtime.h>

#define DIN    9
#define NPAIR  45
#define NTRI   165

// smem basis layout (floats), channel-natural (NOT duplicated):
//  A:   9 rows * 4  =  36  @ 0     (ch: [e0, e1p0, e1p1, e1p2])
//  B:  45 rows * 12 = 540  @ 36    (ch: [e2s0..2, e3s0p0..s1p2, pad3])
//  C: 165 rows * 12 = 1980 @ 576   (ch: [e4s0..3, e5s0p0..s1p2, pad2])
#define SB_TOTAL 2556

typedef unsigned long long u64;

__device__ __forceinline__ u64 pk2(float lo, float hi) {
    u64 r; asm("mov.b64 %0, {%1, %2};" : "=l"(r) : "f"(lo), "f"(hi)); return r;
}
__device__ __forceinline__ void upk2(float& lo, float& hi, u64 v) {
    asm("mov.b64 {%0, %1}, %2;" : "=f"(lo), "=f"(hi) : "l"(v));
}
__device__ __forceinline__ u64 ffma2(u64 a, u64 b, u64 c) {
    u64 d; asm("fma.rn.f32x2 %0, %1, %2, %3;" : "=l"(d) : "l"(a), "l"(b), "l"(c)); return d;
}
__device__ __forceinline__ u64 fmul2(u64 a, u64 b) {
    u64 d; asm("mul.rn.f32x2 %0, %1, %2;" : "=l"(d) : "l"(a), "l"(b)); return d;
}
__device__ __forceinline__ u64 duplo(u64 v) { float lo, hi; upk2(lo, hi, v); return pk2(lo, lo); }
__device__ __forceinline__ u64 duphi(u64 v) { float lo, hi; upk2(lo, hi, v); return pk2(hi, hi); }

// per-item epilogue: scalar weight contraction + store
__device__ __forceinline__ void epilogue(
    const float* TAs, const float* TBs, const float* TCs,
    const float* __restrict__ W0, const float* __restrict__ W1,
    const float* __restrict__ W2, const float* __restrict__ W3,
    const float* __restrict__ W4, const float* __restrict__ W5,
    int e, int m, float* obase)
{
    float o0 = W0[e * 128 + m] * TAs[0];
    #pragma unroll
    for (int s = 0; s < 3; s++) o0 = fmaf(W2[(e * 3 + s) * 128 + m], TBs[s], o0);
    #pragma unroll
    for (int s = 0; s < 4; s++) o0 = fmaf(W4[(e * 4 + s) * 128 + m], TCs[s], o0);

    float o1[3];
    const float w1 = W1[e * 128 + m];
    #pragma unroll
    for (int p = 0; p < 3; p++) o1[p] = w1 * TAs[1 + p];
    #pragma unroll
    for (int s = 0; s < 2; s++) {
        const float w = W3[(e * 2 + s) * 128 + m];
        #pragma unroll
        for (int p = 0; p < 3; p++) o1[p] = fmaf(w, TBs[3 + s * 3 + p], o1[p]);
    }
    #pragma unroll
    for (int s = 0; s < 2; s++) {
        const float w = W5[(e * 2 + s) * 128 + m];
        #pragma unroll
        for (int p = 0; p < 3; p++) o1[p] = fmaf(w, TCs[4 + s * 3 + p], o1[p]);
    }

    obase[m] = o0;
    #pragma unroll
    for (int p = 0; p < 3; p++) obase[128 + m * 3 + p] = o1[p];
}

// ---------------------------------------------------------------------------
// One kernel. Each block: (1) symmetrize bases into its own smem, (2) compute
// 4 nodes x 128 muls with 2 items per thread, channel-packed f32x2 math.
// blockDim = (64, 4).
// ---------------------------------------------------------------------------
__global__ void __launch_bounds__(256, 2)
symcon_kernel(const float* __restrict__ feats,   // (N, 1152)
              const int*   __restrict__ species, // (N,)
              const float* __restrict__ b0, const float* __restrict__ b1,
              const float* __restrict__ b2, const float* __restrict__ b3,
              const float* __restrict__ b4, const float* __restrict__ b5,
              const float* __restrict__ W0, const float* __restrict__ W1,
              const float* __restrict__ W2, const float* __restrict__ W3,
              const float* __restrict__ W4, const float* __restrict__ W5,
              float* __restrict__ out)            // (N, 512)
{
    __shared__ float sb[SB_TOTAL];   // 10224 B

    const int tid = threadIdx.y * 64 + threadIdx.x;

    // ---- fused prep: symmetrize bases into smem ----
    if (tid < DIN) {
        float* row = sb + tid * 4;
        row[0] = b0[tid];
        #pragma unroll
        for (int p = 0; p < 3; p++) row[1 + p] = b1[tid * 3 + p];
    }
    if (tid < NPAIR) {
        // decode pair index -> (a, b), a <= b
        int a = 0, rem = tid;
        while (rem >= DIN - a) { rem -= DIN - a; a++; }
        const int b = a + rem;
        float* row = sb + 36 + tid * 12;
        #pragma unroll
        for (int s = 0; s < 3; s++) {
            float v = b2[(a * 9 + b) * 3 + s];
            if (a != b) v += b2[(b * 9 + a) * 3 + s];
            row[s] = v;
        }
        #pragma unroll
        for (int s = 0; s < 2; s++)
            #pragma unroll
            for (int p = 0; p < 3; p++) {
                float v = b3[((a * 9 + b) * 2 + s) * 3 + p];
                if (a != b) v += b3[((b * 9 + a) * 2 + s) * 3 + p];
                row[3 + s * 3 + p] = v;
            }
        row[9] = 0.f; row[10] = 0.f; row[11] = 0.f;
    }
    if (tid < NTRI) {
        // decode triple index -> (a, b, c), a <= b <= c
        int a = 0, rem = tid;
        for (;; a++) {
            const int cnt = (DIN - a) * (DIN - a + 1) / 2;
            if (rem < cnt) break;
            rem -= cnt;
        }
        int b = a;
        for (;; b++) {
            const int cnt = DIN - b;
            if (rem < cnt) break;
            rem -= cnt;
        }
        const int c = b + rem;

        const int pi[6] = {a, a, b, b, c, c};
        const int pj[6] = {b, c, a, c, a, b};
        const int pk[6] = {c, b, c, a, b, a};
        float acc[10];
        #pragma unroll
        for (int q = 0; q < 10; q++) acc[q] = 0.f;
        for (int q = 0; q < 6; q++) {
            bool dup = false;
            for (int r = 0; r < q; r++)
                if (pi[r] == pi[q] && pj[r] == pj[q] && pk[r] == pk[q]) { dup = true; break; }
            if (dup) continue;
            const int base = (pi[q] * 9 + pj[q]) * 9 + pk[q];
            for (int s = 0; s < 4; s++) acc[s] += b4[base * 4 + s];
            for (int s = 0; s < 2; s++)
                for (int p = 0; p < 3; p++)
                    acc[4 + s * 3 + p] += b5[(base * 2 + s) * 3 + p];
        }
        float* row = sb + 576 + tid * 12;
        #pragma unroll
        for (int q = 0; q < 10; q++) row[q] = acc[q];
        row[10] = 0.f; row[11] = 0.f;
    }
    __syncthreads();

    // smem views (u64 units; A row a at u64 idx a*2, B row pr at 18+pr*6, C row t3 at 288+t3*6)
    const u64* sbu = reinterpret_cast<const u64*>(sb);

    const int m0 = threadIdx.x;          // 0..63
    const int m1 = m0 + 64;
    const int n  = blockIdx.x * 4 + threadIdx.y;
    const int e  = species[n];

    const float* fbase = feats + n * 1152;

    // packed features: lo = item m0, hi = item m1
    u64 f2[9];
    f2[0] = pk2(fbase[m0], fbase[m1]);
    #pragma unroll
    for (int k = 0; k < 3; k++)
        f2[1 + k] = pk2(fbase[128 + m0 * 3 + k], fbase[128 + m1 * 3 + k]);
    #pragma unroll
    for (int k = 0; k < 5; k++)
        f2[4 + k] = pk2(fbase[512 + m0 * 5 + k], fbase[512 + m1 * 5 + k]);

    // channel-pair accumulators, separate per item
    u64 A0[2], A1[2], B0[5], B1[5], C0[5], C1[5];
    #pragma unroll
    for (int q = 0; q < 2; q++) { A0[q] = 0ull; A1[q] = 0ull; }
    #pragma unroll
    for (int q = 0; q < 5; q++) { B0[q] = 0ull; B1[q] = 0ull; C0[q] = 0ull; C1[q] = 0ull; }

    // nu=1
    #pragma unroll
    for (int a = 0; a < 9; a++) {
        const ulonglong2 v = *reinterpret_cast<const ulonglong2*>(sbu + a * 2);
        const u64 d0 = duplo(f2[a]);
        const u64 d1 = duphi(f2[a]);
        A0[0] = ffma2(v.x, d0, A0[0]);
        A0[1] = ffma2(v.y, d0, A0[1]);
        A1[0] = ffma2(v.x, d1, A1[0]);
        A1[1] = ffma2(v.y, d1, A1[1]);
    }

    // nu=2 + nu=3 fused
    {
        int pr = 0, t3 = 0;
        #pragma unroll
        for (int a = 0; a < 9; a++) {
            #pragma unroll
            for (int b = a; b < 9; b++) {
                const u64 Pab = fmul2(f2[a], f2[b]);
                const u64 dp0 = duplo(Pab);
                const u64 dp1 = duphi(Pab);
                {
                    const u64* r = sbu + 18 + pr * 6;
                    const ulonglong2 v01 = *reinterpret_cast<const ulonglong2*>(r);
                    const ulonglong2 v23 = *reinterpret_cast<const ulonglong2*>(r + 2);
                    const u64 v4 = r[4];
                    B0[0] = ffma2(v01.x, dp0, B0[0]);
                    B0[1] = ffma2(v01.y, dp0, B0[1]);
                    B0[2] = ffma2(v23.x, dp0, B0[2]);
                    B0[3] = ffma2(v23.y, dp0, B0[3]);
                    B0[4] = ffma2(v4,    dp0, B0[4]);
                    B1[0] = ffma2(v01.x, dp1, B1[0]);
                    B1[1] = ffma2(v01.y, dp1, B1[1]);
                    B1[2] = ffma2(v23.x, dp1, B1[2]);
                    B1[3] = ffma2(v23.y, dp1, B1[3]);
                    B1[4] = ffma2(v4,    dp1, B1[4]);
                }
                #pragma unroll
                for (int c = b; c < 9; c++) {
                    const u64 Fv = fmul2(Pab, f2[c]);
                    const u64 d0 = duplo(Fv);
                    const u64 d1 = duphi(Fv);
                    const u64* r = sbu + 288 + t3 * 6;
                    const ulonglong2 w01 = *reinterpret_cast<const ulonglong2*>(r);
                    const ulonglong2 w23 = *reinterpret_cast<const ulonglong2*>(r + 2);
                    const u64 w4 = r[4];
                    C0[0] = ffma2(w01.x, d0, C0[0]);
                    C0[1] = ffma2(w01.y, d0, C0[1]);
                    C0[2] = ffma2(w23.x, d0, C0[2]);
                    C0[3] = ffma2(w23.y, d0, C0[3]);
                    C0[4] = ffma2(w4,    d0, C0[4]);
                    C1[0] = ffma2(w01.x, d1, C1[0]);
                    C1[1] = ffma2(w01.y, d1, C1[1]);
                    C1[2] = ffma2(w23.x, d1, C1[2]);
                    C1[3] = ffma2(w23.y, d1, C1[3]);
                    C1[4] = ffma2(w4,    d1, C1[4]);
                    t3++;
                }
                pr++;
            }
        }
    }

    // unpack accumulators and run per-item epilogue
    float* obase = out + n * 512;
    {
        float TAs[4], TBs[10], TCs[10];
        upk2(TAs[0], TAs[1], A0[0]); upk2(TAs[2], TAs[3], A0[1]);
        #pragma unroll
        for (int q = 0; q < 5; q++) upk2(TBs[2 * q], TBs[2 * q + 1], B0[q]);
        #pragma unroll
        for (int q = 0; q < 5; q++) upk2(TCs[2 * q], TCs[2 * q + 1], C0[q]);
        epilogue(TAs, TBs, TCs, W0, W1, W2, W3, W4, W5, e, m0, obase);
    }
    {
        float TAs[4], TBs[10], TCs[10];
        upk2(TAs[0], TAs[1], A1[0]); upk2(TAs[2], TAs[3], A1[1]);
        #pragma unroll
        for (int q = 0; q < 5; q++) upk2(TBs[2 * q], TBs[2 * q + 1], B1[q]);
        #pragma unroll
        for (int q = 0; q < 5; q++) upk2(TCs[2 * q], TCs[2 * q + 1], C1[q]);
        epilogue(TAs, TBs, TCs, W0, W1, W2, W3, W4, W5, e, m1, obase);
    }
}

// ---------------------------------------------------------------------------
extern "C" void kernel_launch(void* const* d_in, const int* in_sizes, int n_in,
                              void* d_out, int out_size)
{
    const float* feats   = (const float*)d_in[0];
    const int*   species = (const int*)  d_in[1];
    const float* b0 = (const float*)d_in[2];
    const float* w0 = (const float*)d_in[3];
    const float* b1 = (const float*)d_in[4];
    const float* w1 = (const float*)d_in[5];
    const float* b2 = (const float*)d_in[6];
    const float* w2 = (const float*)d_in[7];
    const float* b3 = (const float*)d_in[8];
    const float* w3 = (const float*)d_in[9];
    const float* b4 = (const float*)d_in[10];
    const float* w4 = (const float*)d_in[11];
    const float* b5 = (const float*)d_in[12];
    const float* w5 = (const float*)d_in[13];
    float* out = (float*)d_out;

    dim3 block(64, 4);
    dim3 grid(2048 / 4);
    symcon_kernel<<<grid, block>>>(feats, species,
                                   b0, b1, b2, b3, b4, b5,
                                   w0, w1, w2, w3, w4, w5, out);
}